// round 8
// baseline (speedup 1.0000x reference)
#include <cuda_runtime.h>
#include <cuda_bf16.h>
#include <math.h>
#include <stdint.h>

#define NB 16
#define T1V 800
#define T2V 200

extern __shared__ char smem_dyn[];

// Intermediates (no allocation allowed -> __device__ globals)
__device__ float g_kh [NB*512*200];   // key conv1 out (post-relu)
__device__ float g_k  [NB*80*200];    // key encoder out
__device__ float g_qh1[NB*160*800];   // query conv1 out (post-relu)
__device__ float g_qh2[NB*80*800];    // query conv2 out (post-relu)
__device__ float g_q  [NB*80*800];    // query encoder out

// Pre-transposed, zero-padded bf16 weights: Wt[kap][m], kap = kk*CIN + cin
__device__ __nv_bfloat16 g_wt1 [768*512];
__device__ __nv_bfloat16 g_wt2 [512*80];
__device__ __nv_bfloat16 g_wtq1[256*160];
__device__ __nv_bfloat16 g_wtq2[160*80];
__device__ __nv_bfloat16 g_wtq3[ 96*80];

// ---------------- mma/ldmatrix helpers (baseline PTX, sm_103-safe) ----------------
__device__ __forceinline__ uint32_t smem_u32(const void* p) {
    uint32_t a;
    asm("{ .reg .u64 t; cvta.to.shared.u64 t, %1; cvt.u32.u64 %0, t; }" : "=r"(a) : "l"(p));
    return a;
}
__device__ __forceinline__ void ldsm4t(uint32_t r[4], uint32_t addr) {
    asm volatile("ldmatrix.sync.aligned.m8n8.x4.trans.shared.b16 {%0,%1,%2,%3}, [%4];"
                 : "=r"(r[0]), "=r"(r[1]), "=r"(r[2]), "=r"(r[3]) : "r"(addr));
}
__device__ __forceinline__ void mma16816(float c[4], const uint32_t a[4],
                                         uint32_t b0, uint32_t b1) {
    asm volatile("mma.sync.aligned.m16n8k16.row.col.f32.bf16.bf16.f32 "
                 "{%0,%1,%2,%3}, {%4,%5,%6,%7}, {%8,%9}, {%0,%1,%2,%3};"
                 : "+f"(c[0]), "+f"(c[1]), "+f"(c[2]), "+f"(c[3])
                 : "r"(a[0]), "r"(a[1]), "r"(a[2]), "r"(a[3]), "r"(b0), "r"(b1));
}

// ---------------- weight prep ----------------
__device__ __forceinline__ void wt_fill(__nv_bfloat16* dst, const float* W,
                                        int idx, int COUT, int CIN, int KW, int K) {
    int kap = idx / COUT, m = idx - kap * COUT;
    float v = 0.f;
    if (kap < K) {
        int kk = kap / CIN, cin = kap - kk * CIN;
        v = W[m * K + cin * KW + kk];
    }
    dst[idx] = __float2bfloat16(v);
}

__global__ __launch_bounds__(256)
void prep_weights(const float* kw1, const float* kw2, const float* qw1,
                  const float* qw2, const float* qw3) {
    const int s1 = 768*512, s2 = 512*80, s3 = 256*160, s4 = 160*80, s5 = 96*80;
    int idx = blockIdx.x * 256 + threadIdx.x;
    if (idx < s1) { wt_fill(g_wt1, kw1, idx, 512, 256, 3, 768); return; }
    idx -= s1;
    if (idx < s2) { wt_fill(g_wt2, kw2, idx, 80, 512, 1, 512); return; }
    idx -= s2;
    if (idx < s3) { wt_fill(g_wtq1, qw1, idx, 160, 80, 3, 240); return; }
    idx -= s3;
    if (idx < s4) { wt_fill(g_wtq2, qw2, idx, 80, 160, 1, 160); return; }
    idx -= s4;
    if (idx < s5) { wt_fill(g_wtq3, qw3, idx, 80, 80, 1, 80); return; }
}

// ---------------- conv-as-GEMM via bf16 mma.sync (Round-6 proven version) ----------------
template<int CIN, int COUT, int KW, int PAD, bool RELU, int T,
         int WY, int WX, int TM16, int TN8, int NC>
__device__ __forceinline__
void mma_conv(const __nv_bfloat16* __restrict__ Wt, const float* __restrict__ bias,
              const float* __restrict__ X, float* __restrict__ Y,
              int mtile, int ntile)
{
    constexpr int BM = WY * TM16 * 16;
    constexpr int BN = WX * TN8 * 8;     static_assert(BN == 128, "BN must be 128");
    constexpr int K   = CIN * KW;
    constexpr int BMp = BM + 8;
    constexpr int BNp = 136;
    constexpr int AWW = BM / 2;
    constexpr int LAW = 32 * AWW / 256;
    constexpr int LBW = 8;
    constexpr int ABYTES = 32 * BMp * 2;
    constexpr int BBYTES = 32 * BNp * 2;

    const int tid = threadIdx.x;
    const int wid = tid >> 5, lid = tid & 31;
    const int wy = wid / WX, wx = wid - wy * WX;
    const int wm0 = wy * TM16 * 16, wn0 = wx * TN8 * 8;

    uint32_t* A32[2] = { reinterpret_cast<uint32_t*>(smem_dyn),
                         reinterpret_cast<uint32_t*>(smem_dyn + ABYTES) };
    uint32_t* B32[2] = { reinterpret_cast<uint32_t*>(smem_dyn + 2*ABYTES),
                         reinterpret_cast<uint32_t*>(smem_dyn + 2*ABYTES + BBYTES) };
    const uint32_t uS = smem_u32(smem_dyn);
    const uint32_t uA[2] = { uS, uS + ABYTES };
    const uint32_t uB[2] = { uS + 2*ABYTES, uS + 2*ABYTES + BBYTES };

    const int g = lid >> 3, lr = lid & 7;
    const uint32_t a_off = ((lr + ((g & 2) ? 8 : 0)) * BMp + ((g & 1) ? 8 : 0)) * 2;
    const uint32_t b_off = ((lr + ((g & 1) ? 8 : 0)) * BNp + ((g & 2) ? 8 : 0)) * 2;

    float acc[TM16][TN8][4];
#pragma unroll
    for (int i = 0; i < TM16; i++)
#pragma unroll
        for (int j = 0; j < TN8; j++)
#pragma unroll
            for (int r = 0; r < 4; r++) acc[i][j][r] = 0.f;

    const uint32_t* Wt32 = reinterpret_cast<const uint32_t*>(Wt);
    const int awbase = mtile * BM / 2;

    uint32_t ra[LAW], rb[LBW];

    auto loadA = [&](int kc) {
#pragma unroll
        for (int s = 0; s < LAW; s++) {
            int w = tid + s * 256;
            int mp = w % AWW, k = w / AWW;
            ra[s] = Wt32[(size_t)(kc * 32 + k) * (COUT / 2) + awbase + mp];
        }
    };
    auto loadB = [&](int kc) {
#pragma unroll
        for (int s = 0; s < LBW; s++) {
            int w = tid + s * 256;
            int np = w & 63, k = w >> 6;
            int kap = kc * 32 + k;
            int n = ntile * 128 + 2 * np;
            int bb = n / T, t = n - bb * T;
            float v0 = 0.f, v1 = 0.f;
            if (kap < K) {
                if (KW == 1) {
                    const float* xr = X + (size_t)(bb * CIN + kap) * T + t;
                    v0 = xr[0]; v1 = xr[1];
                } else {
                    int kk = kap / CIN, cin = kap - kk * CIN;
                    int tin = t + kk - PAD;
                    const float* xr = X + (size_t)(bb * CIN + cin) * T;
                    if ((unsigned)tin < (unsigned)T)       v0 = xr[tin];
                    if ((unsigned)(tin + 1) < (unsigned)T) v1 = xr[tin + 1];
                }
            }
            __nv_bfloat162 h = __floats2bfloat162_rn(v0, v1);
            rb[s] = *reinterpret_cast<uint32_t*>(&h);
        }
    };
    auto stsA = [&](int p) {
#pragma unroll
        for (int s = 0; s < LAW; s++) {
            int w = tid + s * 256;
            int mp = w % AWW, k = w / AWW;
            A32[p][k * (BMp / 2) + mp] = ra[s];
        }
    };
    auto stsB = [&](int p) {
#pragma unroll
        for (int s = 0; s < LBW; s++) {
            int w = tid + s * 256;
            int np = w & 63, k = w >> 6;
            B32[p][k * (BNp / 2) + np] = rb[s];
        }
    };
    auto compute = [&](int p) {
#pragma unroll
        for (int ks = 0; ks < 32; ks += 16) {
            uint32_t af[TM16][4];
#pragma unroll
            for (int i = 0; i < TM16; i++)
                ldsm4t(af[i], uA[p] + a_off + (ks * BMp + wm0 + 16 * i) * 2);
            uint32_t bf[TN8 / 2][4];
#pragma unroll
            for (int jj = 0; jj < TN8 / 2; jj++)
                ldsm4t(bf[jj], uB[p] + b_off + (ks * BNp + wn0 + 16 * jj) * 2);
#pragma unroll
            for (int i = 0; i < TM16; i++)
#pragma unroll
                for (int j = 0; j < TN8; j++)
                    mma16816(acc[i][j], af[i], bf[j >> 1][(j & 1) * 2], bf[j >> 1][(j & 1) * 2 + 1]);
        }
    };

    loadA(0); loadB(0);
    stsA(0);  stsB(0);
    __syncthreads();

    for (int kc = 0; kc < NC; kc++) {
        int p = kc & 1;
        if (kc + 1 < NC) { loadA(kc + 1); loadB(kc + 1); }
        compute(p);
        if (kc + 1 < NC) { stsA(p ^ 1); stsB(p ^ 1); __syncthreads(); }
    }

#pragma unroll
    for (int i = 0; i < TM16; i++) {
        int r0 = mtile * BM + wm0 + 16 * i + (lid >> 2);
        float bv0 = bias[r0], bv1 = bias[r0 + 8];
#pragma unroll
        for (int j = 0; j < TN8; j++) {
            int n = ntile * 128 + wn0 + 8 * j + (lid & 3) * 2;
            int bb = n / T, t = n - bb * T;
            float2 v0, v1;
            v0.x = acc[i][j][0] + bv0; v0.y = acc[i][j][1] + bv0;
            v1.x = acc[i][j][2] + bv1; v1.y = acc[i][j][3] + bv1;
            if (RELU) {
                v0.x = fmaxf(v0.x, 0.f); v0.y = fmaxf(v0.y, 0.f);
                v1.x = fmaxf(v1.x, 0.f); v1.y = fmaxf(v1.y, 0.f);
            }
            *reinterpret_cast<float2*>(&Y[(size_t)(bb * COUT + r0) * T + t])     = v0;
            *reinterpret_cast<float2*>(&Y[(size_t)(bb * COUT + r0 + 8) * T + t]) = v1;
        }
    }
}

__global__ __launch_bounds__(256)
void fusedA(const float* __restrict__ kb1, const float* __restrict__ keys, float* __restrict__ kh,
            const float* __restrict__ qb1, const float* __restrict__ queries, float* __restrict__ qh1)
{
    int bx = blockIdx.x;
    if (blockIdx.z == 0) {
        if (bx >= 100) return;
        mma_conv<256, 512, 3, 1, true, 200, 2, 4, 4, 4, 24>(g_wt1, kb1, keys, kh, bx / 25, bx % 25);
    } else {
        mma_conv<80, 160, 3, 1, true, 800, 1, 8, 5, 2, 8>(g_wtq1, qb1, queries, qh1, bx / 100, bx % 100);
    }
}

__global__ __launch_bounds__(256)
void fusedB(const float* __restrict__ kb2, const float* __restrict__ kh, float* __restrict__ kout,
            const float* __restrict__ qb2, const float* __restrict__ qh1, float* __restrict__ qh2)
{
    int bx = blockIdx.x;
    if (blockIdx.z == 0) {
        if (bx >= 25) return;
        mma_conv<512, 80, 1, 0, false, 200, 1, 8, 5, 2, 16>(g_wt2, kb2, kh, kout, 0, bx);
    } else {
        mma_conv<160, 80, 1, 0, true, 800, 1, 8, 5, 2, 5>(g_wtq2, qb2, qh1, qh2, 0, bx);
    }
}

__global__ __launch_bounds__(256)
void convC(const float* __restrict__ qb3, const float* __restrict__ qh2, float* __restrict__ q)
{
    mma_conv<80, 80, 1, 0, false, 800, 1, 8, 5, 2, 3>(g_wtq3, qb3, qh2, q, 0, blockIdx.x);
}

// ---------------- attention via HMMA + fused log-softmax ----------------
// Per (batch, 80 t1 rows): S[80 x 256] = q_tile(K=80)^T . k (t2 padded 200->256, masked).
// logits = -5e-4*(q2 + k2 - 2*S); out = logits - lse_row + log(prior + 1e-8).
// 8 warps, warp tile 80(M) x 32(N): TM16=5, TN8=4; K=80 = 5 x k16 exact.
__global__ __launch_bounds__(256)
void attn_mma(const float* __restrict__ q, const float* __restrict__ k,
              const float* __restrict__ prior, float* __restrict__ out)
{
    constexpr int BMp = 88;    // A bf16 row stride
    constexpr int BNp = 264;   // B bf16 row stride
    constexpr int SA  = 0;                    // A: 80 x 88 bf16 = 14080 B
    constexpr int SB  = 14080;                // B: 80 x 264 bf16 = 42240 B
    constexpr int SQ2 = 56320;                // q2: 80 f32
    constexpr int SK2 = 56640;                // k2: 256 f32
    constexpr int SRD = 57664;                // red: 80 x 8 f32 = 2560 B

    const int b   = blockIdx.y;
    const int t10 = blockIdx.x * 80;
    const int tid = threadIdx.x;
    const int wid = tid >> 5, lid = tid & 31;
    const int wn0 = wid * 32;

    __nv_bfloat16* As = reinterpret_cast<__nv_bfloat16*>(smem_dyn + SA);
    __nv_bfloat16* Bs = reinterpret_cast<__nv_bfloat16*>(smem_dyn + SB);
    float* q2s = reinterpret_cast<float*>(smem_dyn + SQ2);
    float* k2s = reinterpret_cast<float*>(smem_dyn + SK2);
    float* red = reinterpret_cast<float*>(smem_dyn + SRD);
    const uint32_t uS = smem_u32(smem_dyn);
    const uint32_t uA = uS + SA, uB = uS + SB;

    // load A: q tile [k=c(80)][m=row(80)], coalesced on m
    for (int idx = tid; idx < 80 * 80; idx += 256) {
        int c = idx / 80, m = idx - c * 80;
        As[c * BMp + m] = __float2bfloat16(q[(size_t)(b * 80 + c) * 800 + t10 + m]);
    }
    // load B: k [k=c(80)][n=t2(256, zero-pad >=200)], coalesced on n
    for (int idx = tid; idx < 80 * 256; idx += 256) {
        int c = idx >> 8, n = idx & 255;
        float v = (n < 200) ? k[(size_t)(b * 80 + c) * 200 + n] : 0.f;
        Bs[c * BNp + n] = __float2bfloat16(v);
    }
    // q2 / k2 in fp32 from global
    if (tid < 80) {
        float s = 0.f;
        const float* qp = q + (size_t)b * 80 * 800 + t10 + tid;
#pragma unroll 8
        for (int c = 0; c < 80; c++) { float v = qp[c * 800]; s += v * v; }
        q2s[tid] = s;
    }
    {
        float s = 0.f;
        if (tid < 200) {
            const float* kp = k + (size_t)b * 80 * 200 + tid;
#pragma unroll 8
            for (int c = 0; c < 80; c++) { float v = kp[c * 200]; s += v * v; }
        }
        k2s[tid] = s;   // 0 for padded cols
    }
    __syncthreads();

    // ---- HMMA mainloop: 5 k16 steps ----
    const int g = lid >> 3, lr = lid & 7;
    const uint32_t a_off = ((lr + ((g & 2) ? 8 : 0)) * BMp + ((g & 1) ? 8 : 0)) * 2;
    const uint32_t b_off = ((lr + ((g & 1) ? 8 : 0)) * BNp + ((g & 2) ? 8 : 0)) * 2;

    float acc[5][4][4];
#pragma unroll
    for (int i = 0; i < 5; i++)
#pragma unroll
        for (int j = 0; j < 4; j++)
#pragma unroll
            for (int r = 0; r < 4; r++) acc[i][j][r] = 0.f;

#pragma unroll
    for (int ks = 0; ks < 80; ks += 16) {
        uint32_t af[5][4];
#pragma unroll
        for (int i = 0; i < 5; i++)
            ldsm4t(af[i], uA + a_off + (ks * BMp + 16 * i) * 2);
        uint32_t bf[2][4];
#pragma unroll
        for (int jj = 0; jj < 2; jj++)
            ldsm4t(bf[jj], uB + b_off + (ks * BNp + wn0 + 16 * jj) * 2);
#pragma unroll
        for (int i = 0; i < 5; i++)
#pragma unroll
            for (int j = 0; j < 4; j++)
                mma16816(acc[i][j], af[i], bf[j >> 1][(j & 1) * 2], bf[j >> 1][(j & 1) * 2 + 1]);
    }

    // ---- logits + row max ----
    const int lq = lid >> 2;      // row-in-m16 (0..7)
    const int lc = (lid & 3) * 2; // col pair base
    float mx[5][2];
#pragma unroll
    for (int i = 0; i < 5; i++) { mx[i][0] = -1e30f; mx[i][1] = -1e30f; }

#pragma unroll
    for (int i = 0; i < 5; i++) {
        float q20 = q2s[16 * i + lq];
        float q21 = q2s[16 * i + lq + 8];
#pragma unroll
        for (int j = 0; j < 4; j++) {
            int c = wn0 + 8 * j + lc;
            bool v = c < 200;
            float k2a = k2s[c], k2b = k2s[c + 1];
            float a0 = v ? -5e-4f * (q20 + k2a - 2.f * acc[i][j][0]) : -1e30f;
            float a1 = v ? -5e-4f * (q20 + k2b - 2.f * acc[i][j][1]) : -1e30f;
            float a2 = v ? -5e-4f * (q21 + k2a - 2.f * acc[i][j][2]) : -1e30f;
            float a3 = v ? -5e-4f * (q21 + k2b - 2.f * acc[i][j][3]) : -1e30f;
            acc[i][j][0] = a0; acc[i][j][1] = a1; acc[i][j][2] = a2; acc[i][j][3] = a3;
            mx[i][0] = fmaxf(mx[i][0], fmaxf(a0, a1));
            mx[i][1] = fmaxf(mx[i][1], fmaxf(a2, a3));
        }
    }
    // quad reduce (lanes sharing a row differ only in lid&3)
#pragma unroll
    for (int o = 1; o <= 2; o <<= 1)
#pragma unroll
        for (int i = 0; i < 5; i++) {
            mx[i][0] = fmaxf(mx[i][0], __shfl_xor_sync(0xFFFFFFFFu, mx[i][0], o));
            mx[i][1] = fmaxf(mx[i][1], __shfl_xor_sync(0xFFFFFFFFu, mx[i][1], o));
        }
    if ((lid & 3) == 0)
#pragma unroll
        for (int i = 0; i < 5; i++) {
            red[(16 * i + lq) * 8 + wid]     = mx[i][0];
            red[(16 * i + lq + 8) * 8 + wid] = mx[i][1];
        }
    __syncthreads();

    float rmx[5][2];
#pragma unroll
    for (int i = 0; i < 5; i++)
#pragma unroll
        for (int h = 0; h < 2; h++) {
            const float* rr = &red[(16 * i + lq + 8 * h) * 8];
            float m = rr[0];
#pragma unroll
            for (int w = 1; w < 8; w++) m = fmaxf(m, rr[w]);
            rmx[i][h] = m;
        }
    __syncthreads();   // before red reuse

    // ---- exp sums ----
    float sm[5][2];
#pragma unroll
    for (int i = 0; i < 5; i++) { sm[i][0] = 0.f; sm[i][1] = 0.f; }
#pragma unroll
    for (int i = 0; i < 5; i++)
#pragma unroll
        for (int j = 0; j < 4; j++) {
            sm[i][0] += __expf(acc[i][j][0] - rmx[i][0]) + __expf(acc[i][j][1] - rmx[i][0]);
            sm[i][1] += __expf(acc[i][j][2] - rmx[i][1]) + __expf(acc[i][j][3] - rmx[i][1]);
        }
#pragma unroll
    for (int o = 1; o <= 2; o <<= 1)
#pragma unroll
        for (int i = 0; i < 5; i++) {
            sm[i][0] += __shfl_xor_sync(0xFFFFFFFFu, sm[i][0], o);
            sm[i][1] += __shfl_xor_sync(0xFFFFFFFFu, sm[i][1], o);
        }
    if ((lid & 3) == 0)
#pragma unroll
        for (int i = 0; i < 5; i++) {
            red[(16 * i + lq) * 8 + wid]     = sm[i][0];
            red[(16 * i + lq + 8) * 8 + wid] = sm[i][1];
        }
    __syncthreads();

    float lse[5][2];
#pragma unroll
    for (int i = 0; i < 5; i++)
#pragma unroll
        for (int h = 0; h < 2; h++) {
            const float* rr = &red[(16 * i + lq + 8 * h) * 8];
            float s = 0.f;
#pragma unroll
            for (int w = 0; w < 8; w++) s += rr[w];
            lse[i][h] = rmx[i][h] + __logf(s);
        }

    // ---- store: out = logits - lse + log(prior + 1e-8) ----
#pragma unroll
    for (int i = 0; i < 5; i++)
#pragma unroll
        for (int j = 0; j < 4; j++) {
            int c = wn0 + 8 * j + lc;
            if (c < 200) {
                size_t g0 = (size_t)(b * 800 + t10 + 16 * i + lq) * 200 + c;
                size_t g1 = g0 + 8 * 200;
                float2 p0 = *reinterpret_cast<const float2*>(prior + g0);
                float2 p1 = *reinterpret_cast<const float2*>(prior + g1);
                float2 o0, o1;
                o0.x = acc[i][j][0] - lse[i][0] + __logf(p0.x + 1e-8f);
                o0.y = acc[i][j][1] - lse[i][0] + __logf(p0.y + 1e-8f);
                o1.x = acc[i][j][2] - lse[i][1] + __logf(p1.x + 1e-8f);
                o1.y = acc[i][j][3] - lse[i][1] + __logf(p1.y + 1e-8f);
                *reinterpret_cast<float2*>(out + g0) = o0;
                *reinterpret_cast<float2*>(out + g1) = o1;
            }
        }
}

// ---------------- launcher ----------------
extern "C" void kernel_launch(void* const* d_in, const int* in_sizes, int n_in,
                              void* d_out, int out_size)
{
    const float* queries = (const float*)d_in[0];   // (16, 80, 800)
    const float* keys    = (const float*)d_in[1];   // (16, 256, 200)
    const float* prior   = (const float*)d_in[2];   // (16, 800, 200)
    const float* kw1 = (const float*)d_in[3];
    const float* kb1 = (const float*)d_in[4];
    const float* kw2 = (const float*)d_in[5];
    const float* kb2 = (const float*)d_in[6];
    const float* qw1 = (const float*)d_in[7];
    const float* qb1 = (const float*)d_in[8];
    const float* qw2 = (const float*)d_in[9];
    const float* qb2 = (const float*)d_in[10];
    const float* qw3 = (const float*)d_in[11];
    const float* qb3 = (const float*)d_in[12];
    float* out = (float*)d_out;

    float *p_kh, *p_k, *p_qh1, *p_qh2, *p_q;
    cudaGetSymbolAddress((void**)&p_kh,  g_kh);
    cudaGetSymbolAddress((void**)&p_k,   g_k);
    cudaGetSymbolAddress((void**)&p_qh1, g_qh1);
    cudaGetSymbolAddress((void**)&p_qh2, g_qh2);
    cudaGetSymbolAddress((void**)&p_q,   g_q);

    // 0) weight transpose/convert
    prep_weights<<<1937, 256>>>(kw1, kw2, qw1, qw2, qw3);

    const int smemA = 2 * (32 * 136 * 2) + 2 * (32 * 136 * 2);   // 34816
    const int smemB = 2 * (32 * 88 * 2)  + 2 * (32 * 136 * 2);   // 28672

    // 1) k1 (100) + q1 (200)
    fusedA<<<dim3(200, 1, 2), 256, smemA>>>(kb1, keys, p_kh, qb1, queries, p_qh1);
    // 2) k2 (25) + q2 (100)
    fusedB<<<dim3(100, 1, 2), 256, smemB>>>(kb2, p_kh, p_k, qb2, p_qh1, p_qh2);
    // 3) q3 (100)
    convC<<<dim3(100, 1, 1), 256, smemB>>>(qb3, p_qh2, p_q);

    // 4) HMMA attention + fused log-softmax + prior  (160 CTAs)
    const int smemF = 57664 + 2560;   // 60224 B
    cudaFuncSetAttribute(attn_mma, cudaFuncAttributeMaxDynamicSharedMemorySize, smemF);
    attn_mma<<<dim3(10, 16), 256, smemF>>>(p_q, p_k, prior, out);
}

// round 9
// speedup vs baseline: 1.3882x; 1.3882x over previous
#include <cuda_runtime.h>
#include <cuda_bf16.h>
#include <math.h>
#include <stdint.h>

#define NB 16
#define T1V 800
#define T2V 200

typedef unsigned long long ull;

extern __shared__ char smem_dyn[];

// Intermediates (no allocation allowed -> __device__ globals)
__device__ float g_kh [NB*512*200];   // key conv1 out (post-relu)
__device__ float g_k  [NB*80*200];    // key encoder out
__device__ float g_qh1[NB*160*800];   // query conv1 out (post-relu)
__device__ float g_qh2[NB*80*800];    // query conv2 out (post-relu)
__device__ float g_q  [NB*80*800];    // query encoder out

// Pre-transposed, zero-padded bf16 weights: Wt[kap][m], kap = kk*CIN + cin
__device__ __nv_bfloat16 g_wt1 [768*512];
__device__ __nv_bfloat16 g_wt2 [512*80];
__device__ __nv_bfloat16 g_wtq1[256*160];
__device__ __nv_bfloat16 g_wtq2[160*80];
__device__ __nv_bfloat16 g_wtq3[ 96*80];

// Packed dual-FMA (sm_103a): d.lo += a.lo*b.lo ; d.hi += a.hi*b.hi
#define FFMA2(d, a, b) asm("fma.rn.f32x2 %0, %1, %2, %0;" : "+l"(d) : "l"(a), "l"(b))
#define UNPACK2(lo, hi, p) asm("mov.b64 {%0, %1}, %2;" : "=f"(lo), "=f"(hi) : "l"(p))
#define PACK2(d, lo, hi) asm("mov.b64 %0, {%1, %2};" : "=l"(d) : "f"(lo), "f"(hi))

// ---------------- mma/ldmatrix helpers (baseline PTX, sm_103-safe) ----------------
__device__ __forceinline__ uint32_t smem_u32(const void* p) {
    uint32_t a;
    asm("{ .reg .u64 t; cvta.to.shared.u64 t, %1; cvt.u32.u64 %0, t; }" : "=r"(a) : "l"(p));
    return a;
}
__device__ __forceinline__ void ldsm4t(uint32_t r[4], uint32_t addr) {
    asm volatile("ldmatrix.sync.aligned.m8n8.x4.trans.shared.b16 {%0,%1,%2,%3}, [%4];"
                 : "=r"(r[0]), "=r"(r[1]), "=r"(r[2]), "=r"(r[3]) : "r"(addr));
}
__device__ __forceinline__ void mma16816(float c[4], const uint32_t a[4],
                                         uint32_t b0, uint32_t b1) {
    asm volatile("mma.sync.aligned.m16n8k16.row.col.f32.bf16.bf16.f32 "
                 "{%0,%1,%2,%3}, {%4,%5,%6,%7}, {%8,%9}, {%0,%1,%2,%3};"
                 : "+f"(c[0]), "+f"(c[1]), "+f"(c[2]), "+f"(c[3])
                 : "r"(a[0]), "r"(a[1]), "r"(a[2]), "r"(a[3]), "r"(b0), "r"(b1));
}

// ---------------- weight prep ----------------
__device__ __forceinline__ void wt_fill(__nv_bfloat16* dst, const float* W,
                                        int idx, int COUT, int CIN, int KW, int K) {
    int kap = idx / COUT, m = idx - kap * COUT;
    float v = 0.f;
    if (kap < K) {
        int kk = kap / CIN, cin = kap - kk * CIN;
        v = W[m * K + cin * KW + kk];
    }
    dst[idx] = __float2bfloat16(v);
}

__global__ __launch_bounds__(256)
void prep_weights(const float* kw1, const float* kw2, const float* qw1,
                  const float* qw2, const float* qw3) {
    const int s1 = 768*512, s2 = 512*80, s3 = 256*160, s4 = 160*80, s5 = 96*80;
    int idx = blockIdx.x * 256 + threadIdx.x;
    if (idx < s1) { wt_fill(g_wt1, kw1, idx, 512, 256, 3, 768); return; }
    idx -= s1;
    if (idx < s2) { wt_fill(g_wt2, kw2, idx, 80, 512, 1, 512); return; }
    idx -= s2;
    if (idx < s3) { wt_fill(g_wtq1, qw1, idx, 160, 80, 3, 240); return; }
    idx -= s3;
    if (idx < s4) { wt_fill(g_wtq2, qw2, idx, 80, 160, 1, 160); return; }
    idx -= s4;
    if (idx < s5) { wt_fill(g_wtq3, qw3, idx, 80, 80, 1, 80); return; }
}

// ---------------- conv-as-GEMM via bf16 mma.sync (Round-6 proven version) ----------------
template<int CIN, int COUT, int KW, int PAD, bool RELU, int T,
         int WY, int WX, int TM16, int TN8, int NC>
__device__ __forceinline__
void mma_conv(const __nv_bfloat16* __restrict__ Wt, const float* __restrict__ bias,
              const float* __restrict__ X, float* __restrict__ Y,
              int mtile, int ntile)
{
    constexpr int BM = WY * TM16 * 16;
    constexpr int BN = WX * TN8 * 8;     static_assert(BN == 128, "BN must be 128");
    constexpr int K   = CIN * KW;
    constexpr int BMp = BM + 8;
    constexpr int BNp = 136;
    constexpr int AWW = BM / 2;
    constexpr int LAW = 32 * AWW / 256;
    constexpr int LBW = 8;
    constexpr int ABYTES = 32 * BMp * 2;
    constexpr int BBYTES = 32 * BNp * 2;

    const int tid = threadIdx.x;
    const int wid = tid >> 5, lid = tid & 31;
    const int wy = wid / WX, wx = wid - wy * WX;
    const int wm0 = wy * TM16 * 16, wn0 = wx * TN8 * 8;

    uint32_t* A32[2] = { reinterpret_cast<uint32_t*>(smem_dyn),
                         reinterpret_cast<uint32_t*>(smem_dyn + ABYTES) };
    uint32_t* B32[2] = { reinterpret_cast<uint32_t*>(smem_dyn + 2*ABYTES),
                         reinterpret_cast<uint32_t*>(smem_dyn + 2*ABYTES + BBYTES) };
    const uint32_t uS = smem_u32(smem_dyn);
    const uint32_t uA[2] = { uS, uS + ABYTES };
    const uint32_t uB[2] = { uS + 2*ABYTES, uS + 2*ABYTES + BBYTES };

    const int g = lid >> 3, lr = lid & 7;
    const uint32_t a_off = ((lr + ((g & 2) ? 8 : 0)) * BMp + ((g & 1) ? 8 : 0)) * 2;
    const uint32_t b_off = ((lr + ((g & 1) ? 8 : 0)) * BNp + ((g & 2) ? 8 : 0)) * 2;

    float acc[TM16][TN8][4];
#pragma unroll
    for (int i = 0; i < TM16; i++)
#pragma unroll
        for (int j = 0; j < TN8; j++)
#pragma unroll
            for (int r = 0; r < 4; r++) acc[i][j][r] = 0.f;

    const uint32_t* Wt32 = reinterpret_cast<const uint32_t*>(Wt);
    const int awbase = mtile * BM / 2;

    uint32_t ra[LAW], rb[LBW];

    auto loadA = [&](int kc) {
#pragma unroll
        for (int s = 0; s < LAW; s++) {
            int w = tid + s * 256;
            int mp = w % AWW, k = w / AWW;
            ra[s] = Wt32[(size_t)(kc * 32 + k) * (COUT / 2) + awbase + mp];
        }
    };
    auto loadB = [&](int kc) {
#pragma unroll
        for (int s = 0; s < LBW; s++) {
            int w = tid + s * 256;
            int np = w & 63, k = w >> 6;
            int kap = kc * 32 + k;
            int n = ntile * 128 + 2 * np;
            int bb = n / T, t = n - bb * T;
            float v0 = 0.f, v1 = 0.f;
            if (kap < K) {
                if (KW == 1) {
                    const float* xr = X + (size_t)(bb * CIN + kap) * T + t;
                    v0 = xr[0]; v1 = xr[1];
                } else {
                    int kk = kap / CIN, cin = kap - kk * CIN;
                    int tin = t + kk - PAD;
                    const float* xr = X + (size_t)(bb * CIN + cin) * T;
                    if ((unsigned)tin < (unsigned)T)       v0 = xr[tin];
                    if ((unsigned)(tin + 1) < (unsigned)T) v1 = xr[tin + 1];
                }
            }
            __nv_bfloat162 h = __floats2bfloat162_rn(v0, v1);
            rb[s] = *reinterpret_cast<uint32_t*>(&h);
        }
    };
    auto stsA = [&](int p) {
#pragma unroll
        for (int s = 0; s < LAW; s++) {
            int w = tid + s * 256;
            int mp = w % AWW, k = w / AWW;
            A32[p][k * (BMp / 2) + mp] = ra[s];
        }
    };
    auto stsB = [&](int p) {
#pragma unroll
        for (int s = 0; s < LBW; s++) {
            int w = tid + s * 256;
            int np = w & 63, k = w >> 6;
            B32[p][k * (BNp / 2) + np] = rb[s];
        }
    };
    auto compute = [&](int p) {
#pragma unroll
        for (int ks = 0; ks < 32; ks += 16) {
            uint32_t af[TM16][4];
#pragma unroll
            for (int i = 0; i < TM16; i++)
                ldsm4t(af[i], uA[p] + a_off + (ks * BMp + wm0 + 16 * i) * 2);
            uint32_t bf[TN8 / 2][4];
#pragma unroll
            for (int jj = 0; jj < TN8 / 2; jj++)
                ldsm4t(bf[jj], uB[p] + b_off + (ks * BNp + wn0 + 16 * jj) * 2);
#pragma unroll
            for (int i = 0; i < TM16; i++)
#pragma unroll
                for (int j = 0; j < TN8; j++)
                    mma16816(acc[i][j], af[i], bf[j >> 1][(j & 1) * 2], bf[j >> 1][(j & 1) * 2 + 1]);
        }
    };

    loadA(0); loadB(0);
    stsA(0);  stsB(0);
    __syncthreads();

    for (int kc = 0; kc < NC; kc++) {
        int p = kc & 1;
        if (kc + 1 < NC) { loadA(kc + 1); loadB(kc + 1); }
        compute(p);
        if (kc + 1 < NC) { stsA(p ^ 1); stsB(p ^ 1); __syncthreads(); }
    }

#pragma unroll
    for (int i = 0; i < TM16; i++) {
        int r0 = mtile * BM + wm0 + 16 * i + (lid >> 2);
        float bv0 = bias[r0], bv1 = bias[r0 + 8];
#pragma unroll
        for (int j = 0; j < TN8; j++) {
            int n = ntile * 128 + wn0 + 8 * j + (lid & 3) * 2;
            int bb = n / T, t = n - bb * T;
            float2 v0, v1;
            v0.x = acc[i][j][0] + bv0; v0.y = acc[i][j][1] + bv0;
            v1.x = acc[i][j][2] + bv1; v1.y = acc[i][j][3] + bv1;
            if (RELU) {
                v0.x = fmaxf(v0.x, 0.f); v0.y = fmaxf(v0.y, 0.f);
                v1.x = fmaxf(v1.x, 0.f); v1.y = fmaxf(v1.y, 0.f);
            }
            *reinterpret_cast<float2*>(&Y[(size_t)(bb * COUT + r0) * T + t])     = v0;
            *reinterpret_cast<float2*>(&Y[(size_t)(bb * COUT + r0 + 8) * T + t]) = v1;
        }
    }
}

__global__ __launch_bounds__(256)
void fusedA(const float* __restrict__ kb1, const float* __restrict__ keys, float* __restrict__ kh,
            const float* __restrict__ qb1, const float* __restrict__ queries, float* __restrict__ qh1)
{
    int bx = blockIdx.x;
    if (blockIdx.z == 0) {
        if (bx >= 100) return;
        mma_conv<256, 512, 3, 1, true, 200, 2, 4, 4, 4, 24>(g_wt1, kb1, keys, kh, bx / 25, bx % 25);
    } else {
        mma_conv<80, 160, 3, 1, true, 800, 1, 8, 5, 2, 8>(g_wtq1, qb1, queries, qh1, bx / 100, bx % 100);
    }
}

__global__ __launch_bounds__(256)
void fusedB(const float* __restrict__ kb2, const float* __restrict__ kh, float* __restrict__ kout,
            const float* __restrict__ qb2, const float* __restrict__ qh1, float* __restrict__ qh2)
{
    int bx = blockIdx.x;
    if (blockIdx.z == 0) {
        if (bx >= 25) return;
        mma_conv<512, 80, 1, 0, false, 200, 1, 8, 5, 2, 16>(g_wt2, kb2, kh, kout, 0, bx);
    } else {
        mma_conv<160, 80, 1, 0, true, 800, 1, 8, 5, 2, 5>(g_wtq2, qb2, qh1, qh2, 0, bx);
    }
}

__global__ __launch_bounds__(256)
void convC(const float* __restrict__ qb3, const float* __restrict__ qh2, float* __restrict__ q)
{
    mma_conv<80, 80, 1, 0, false, 800, 1, 8, 5, 2, 3>(g_wtq3, qb3, qh2, q, 0, blockIdx.x);
}

// ---------------- final attention: 1 row per thread, pair-packed FFMA2 ----------------
// Per (batch, 32 t1 rows). Thread (row = tid>>3, e = tid&7) owns t2 pairs
// t2 = 2e + 16j, j = 0..12 (pairs with t2 >= 200 masked). k loads are LDS.64,
// MACs are fma.rn.f32x2. Row reductions: width-8 xor shuffles.
__global__ __launch_bounds__(256)
void attn_final(const float* __restrict__ q, const float* __restrict__ k,
                const float* __restrict__ prior, float* __restrict__ out)
{
    float* sm   = reinterpret_cast<float*>(smem_dyn);
    float* ksh  = sm;                 // [80][200] = 16000
    float* qsh  = sm + 16000;         // [32][81] transposed, padded
    float* k2sh = qsh + 32 * 81;      // [208] (padded; >=200 garbage, masked)
    float* q2sh = k2sh + 208;         // [32]
    // total: 16000+2592+208+32 = 18832 floats; +8 pad for OOB LDS.64 reads

    const int b   = blockIdx.y;
    const int t10 = blockIdx.x * 32;
    const int tid = threadIdx.x;

    for (int i = tid; i < 80 * 200; i += 256)
        ksh[i] = k[b * 16000 + i];
    for (int i = tid; i < 80 * 32; i += 256) {
        int c = i >> 5, tl = i & 31;
        qsh[tl * 81 + c] = q[(b * 80 + c) * 800 + t10 + tl];
    }
    __syncthreads();

    if (tid < 200) {
        float s = 0.f;
#pragma unroll
        for (int c = 0; c < 80; c++) { float v = ksh[c * 200 + tid]; s += v * v; }
        k2sh[tid] = s;
    }
    if (tid < 32) {
        float s = 0.f;
#pragma unroll
        for (int c = 0; c < 80; c++) { float v = qsh[tid * 81 + c]; s += v * v; }
        q2sh[tid] = s;
    }
    __syncthreads();

    const int row = tid >> 3;   // 0..31
    const int e   = tid & 7;    // pair-lane within row

    ull acc2[13];
#pragma unroll
    for (int j = 0; j < 13; j++) acc2[j] = 0ull;

    const float* qrow = &qsh[row * 81];
#pragma unroll 4
    for (int c = 0; c < 80; c++) {
        float qv = qrow[c];
        ull qq; PACK2(qq, qv, qv);
        const ull* kp = reinterpret_cast<const ull*>(&ksh[c * 200]) + e;
#pragma unroll
        for (int j = 0; j < 13; j++) {
            // j==12, e>=4 reads in-bounds-but-stale smem; pair discarded below.
            FFMA2(acc2[j], qq, kp[8 * j]);
        }
    }

    const float q2v = q2sh[row];
    float a0[13], a1[13];
    float mx = -1e30f;
#pragma unroll
    for (int j = 0; j < 13; j++) {
        int t2 = 2 * e + 16 * j;
        float lo, hi; UNPACK2(lo, hi, acc2[j]);
        if (t2 < 200) {
            float2 k2 = *reinterpret_cast<const float2*>(&k2sh[t2]);
            a0[j] = -5e-4f * (q2v + k2.x - 2.f * lo);
            a1[j] = -5e-4f * (q2v + k2.y - 2.f * hi);
            mx = fmaxf(mx, fmaxf(a0[j], a1[j]));
        } else {
            a0[j] = -1e30f; a1[j] = -1e30f;
        }
    }
#pragma unroll
    for (int o = 4; o >= 1; o >>= 1)
        mx = fmaxf(mx, __shfl_xor_sync(0xFFFFFFFFu, mx, o));

    float s = 0.f;
#pragma unroll
    for (int j = 0; j < 13; j++) {
        int t2 = 2 * e + 16 * j;
        if (t2 < 200)
            s += __expf(a0[j] - mx) + __expf(a1[j] - mx);
    }
#pragma unroll
    for (int o = 4; o >= 1; o >>= 1)
        s += __shfl_xor_sync(0xFFFFFFFFu, s, o);

    float lse = mx + __logf(s);

    const size_t rbase = (size_t)(b * T1V + t10 + row) * T2V;
#pragma unroll
    for (int j = 0; j < 13; j++) {
        int t2 = 2 * e + 16 * j;
        if (t2 < 200) {
            float2 p = *reinterpret_cast<const float2*>(&prior[rbase + t2]);
            float2 o2;
            o2.x = a0[j] - lse + __logf(p.x + 1e-8f);
            o2.y = a1[j] - lse + __logf(p.y + 1e-8f);
            *reinterpret_cast<float2*>(&out[rbase + t2]) = o2;
        }
    }
}

// ---------------- launcher ----------------
extern "C" void kernel_launch(void* const* d_in, const int* in_sizes, int n_in,
                              void* d_out, int out_size)
{
    const float* queries = (const float*)d_in[0];   // (16, 80, 800)
    const float* keys    = (const float*)d_in[1];   // (16, 256, 200)
    const float* prior   = (const float*)d_in[2];   // (16, 800, 200)
    const float* kw1 = (const float*)d_in[3];
    const float* kb1 = (const float*)d_in[4];
    const float* kw2 = (const float*)d_in[5];
    const float* kb2 = (const float*)d_in[6];
    const float* qw1 = (const float*)d_in[7];
    const float* qb1 = (const float*)d_in[8];
    const float* qw2 = (const float*)d_in[9];
    const float* qb2 = (const float*)d_in[10];
    const float* qw3 = (const float*)d_in[11];
    const float* qb3 = (const float*)d_in[12];
    float* out = (float*)d_out;

    float *p_kh, *p_k, *p_qh1, *p_qh2, *p_q;
    cudaGetSymbolAddress((void**)&p_kh,  g_kh);
    cudaGetSymbolAddress((void**)&p_k,   g_k);
    cudaGetSymbolAddress((void**)&p_qh1, g_qh1);
    cudaGetSymbolAddress((void**)&p_qh2, g_qh2);
    cudaGetSymbolAddress((void**)&p_q,   g_q);

    // 0) weight transpose/convert
    prep_weights<<<1937, 256>>>(kw1, kw2, qw1, qw2, qw3);

    const int smemA = 2 * (32 * 136 * 2) + 2 * (32 * 136 * 2);   // 34816
    const int smemB = 2 * (32 * 88 * 2)  + 2 * (32 * 136 * 2);   // 28672

    // 1) k1 (100) + q1 (200)
    fusedA<<<dim3(200, 1, 2), 256, smemA>>>(kb1, keys, p_kh, qb1, queries, p_qh1);
    // 2) k2 (25) + q2 (100)
    fusedB<<<dim3(100, 1, 2), 256, smemB>>>(kb2, p_kh, p_k, qb2, p_qh1, p_qh2);
    // 3) q3 (100)
    convC<<<dim3(100, 1, 1), 256, smemB>>>(qb3, p_qh2, p_q);

    // 4) distance + log-softmax + prior (400 CTAs)
    const int smemF = (16000 + 32 * 81 + 208 + 32 + 8) * (int)sizeof(float);  // 75360 B
    cudaFuncSetAttribute(attn_final, cudaFuncAttributeMaxDynamicSharedMemorySize, smemF);
    attn_final<<<dim3(25, 16), 256, smemF>>>(p_q, p_k, prior, out);
}